// round 1
// baseline (speedup 1.0000x reference)
#include <cuda_runtime.h>

// CapsNet dynamic routing, fully fused.
// x:  [B=256, N=1152, Ci=8]  fp32
// W:  [C=10, N=1152, Ci=8, Co=16] fp32
// out:[C, B, Co] fp32   (== [C,B,1,1,Co])
//
// Block = (c, pair of b). u[bt][n][co] lives in SMEM; 3 routing iterations
// run entirely on SMEM. W streams through L2 (fits, 5.9MB); b-tiling (BT=2)
// halves W L2 traffic.

static constexpr int kB  = 256;
static constexpr int kN  = 1152;
static constexpr int kCi = 8;
static constexpr int kC  = 10;
static constexpr int kCo = 16;
static constexpr int kBT = 2;        // batches per block
static constexpr int kThreads = 512;
static constexpr int kUP = 17;       // padded row stride for u (bank-conflict-free)

struct Smem {
    float u[kBT][kN][kUP];   // priors, padded rows
    float lg[kBT][kN];       // logits
    float pr[kBT][kN];       // exp(logit - max)
    float red[kBT][16][16];  // group partials for s-accum
    float vv[kBT][kCo];      // squashed output vector
    float redw[kBT][8];      // per-warp reduction scratch
};

__global__ __launch_bounds__(kThreads, 1)
void caps_routing_kernel(const float* __restrict__ x,
                         const float* __restrict__ W,
                         float* __restrict__ out)
{
    extern __shared__ unsigned char smem_u8[];
    Smem& sm = *reinterpret_cast<Smem*>(smem_u8);

    const int tid = threadIdx.x;
    const int c  = blockIdx.y;
    const int b0 = blockIdx.x * kBT;

    // ---------------- Phase 1: priors u[bt][n][co] = x[b,n,:] @ W[c,n,:,:] ----
    // thread -> (co4 = tid&3 covering 4 Co via float4, nloc = tid>>2), 9 passes of 128 n.
    {
        const int co4  = tid & 3;
        const int nloc = tid >> 2;                   // 0..127
        const float4* __restrict__ W4 = reinterpret_cast<const float4*>(W);
        const float4* __restrict__ X4 = reinterpret_cast<const float4*>(x);

        #pragma unroll 1
        for (int pass = 0; pass < kN / 128; ++pass) {
            const int n = pass * 128 + nloc;

            float4 xa0 = X4[(b0 * kN + n) * 2 + 0];
            float4 xb0 = X4[(b0 * kN + n) * 2 + 1];
            float4 xa1 = X4[((b0 + 1) * kN + n) * 2 + 0];
            float4 xb1 = X4[((b0 + 1) * kN + n) * 2 + 1];
            float x0v[8] = {xa0.x, xa0.y, xa0.z, xa0.w, xb0.x, xb0.y, xb0.z, xb0.w};
            float x1v[8] = {xa1.x, xa1.y, xa1.z, xa1.w, xb1.x, xb1.y, xb1.z, xb1.w};

            float4 a0 = make_float4(0.f, 0.f, 0.f, 0.f);
            float4 a1 = make_float4(0.f, 0.f, 0.f, 0.f);
            // W[(c*N+n)*Ci + i][co4*4 .. +3] as float4: index ((c*N+n)*8 + i)*4 + co4
            const int wbase = ((c * kN + n) * kCi) * 4 + co4;
            #pragma unroll
            for (int i = 0; i < kCi; ++i) {
                float4 w = W4[wbase + i * 4];
                a0.x += x0v[i] * w.x; a0.y += x0v[i] * w.y;
                a0.z += x0v[i] * w.z; a0.w += x0v[i] * w.w;
                a1.x += x1v[i] * w.x; a1.y += x1v[i] * w.y;
                a1.z += x1v[i] * w.z; a1.w += x1v[i] * w.w;
            }
            float* u0 = &sm.u[0][n][co4 * 4];
            float* u1 = &sm.u[1][n][co4 * 4];
            u0[0] = a0.x; u0[1] = a0.y; u0[2] = a0.z; u0[3] = a0.w;
            u1[0] = a1.x; u1[1] = a1.y; u1[2] = a1.z; u1[3] = a1.w;
        }
    }
    __syncthreads();

    // ---------------- Phase 2: routing (each 256-thread half owns one b) ------
    const int bsel = tid >> 8;           // 0 or 1
    const int t    = tid & 255;
    const int b    = b0 + bsel;
    const int g    = t >> 4;             // 0..15 (n-group)
    const int co   = t & 15;

    const float* __restrict__ U = &sm.u[bsel][0][0];
    float* __restrict__ LG = sm.lg[bsel];
    float* __restrict__ PR = sm.pr[bsel];

    // ---- iteration 0: probs uniform = 1/N ----
    {
        float partial = 0.f;
        #pragma unroll 4
        for (int k = 0; k < kN / 16; ++k)
            partial += U[(k * 16 + g) * kUP + co];
        sm.red[bsel][g][co] = partial;
        __syncthreads();

        if (t < 16) {
            float s = 0.f;
            #pragma unroll
            for (int gg = 0; gg < 16; ++gg) s += sm.red[bsel][gg][t];
            s *= (1.0f / kN);
            float sq = s * s;
            #pragma unroll
            for (int off = 8; off; off >>= 1)
                sq += __shfl_xor_sync(0x0000FFFFu, sq, off);
            sm.vv[bsel][t] = s * sqrtf(sq) / (1.0f + sq);
        }
        __syncthreads();

        // logit init: lg[n] = dot(u[n,:], v)
        for (int n = t; n < kN; n += 256) {
            float d = 0.f;
            #pragma unroll
            for (int cc = 0; cc < kCo; ++cc)
                d += U[n * kUP + cc] * sm.vv[bsel][cc];
            LG[n] = d;
        }
        __syncthreads();
    }

    // ---- iterations 1, 2 ----
    #pragma unroll 1
    for (int it = 1; it < 3; ++it) {
        // max over logits
        float m = -1e30f;
        for (int n = t; n < kN; n += 256) m = fmaxf(m, LG[n]);
        #pragma unroll
        for (int off = 16; off; off >>= 1)
            m = fmaxf(m, __shfl_xor_sync(0xFFFFFFFFu, m, off));
        if ((t & 31) == 0) sm.redw[bsel][t >> 5] = m;
        __syncthreads();
        float mm = sm.redw[bsel][0];
        #pragma unroll
        for (int w = 1; w < 8; ++w) mm = fmaxf(mm, sm.redw[bsel][w]);

        // e = exp(lg - m), Z = sum e
        float zp = 0.f;
        for (int n = t; n < kN; n += 256) {
            float e = __expf(LG[n] - mm);
            PR[n] = e;
            zp += e;
        }
        #pragma unroll
        for (int off = 16; off; off >>= 1)
            zp += __shfl_xor_sync(0xFFFFFFFFu, zp, off);
        __syncthreads();                 // redw consumers (mm) done
        if ((t & 31) == 0) sm.redw[bsel][t >> 5] = zp;
        __syncthreads();
        float Z = 0.f;
        #pragma unroll
        for (int w = 0; w < 8; ++w) Z += sm.redw[bsel][w];
        const float Zinv = 1.0f / Z;

        // s[co] = (1/Z) * sum_n e_n * u[n][co]
        float partial = 0.f;
        #pragma unroll 4
        for (int k = 0; k < kN / 16; ++k) {
            const int n = k * 16 + g;
            partial += PR[n] * U[n * kUP + co];
        }
        sm.red[bsel][g][co] = partial;
        __syncthreads();

        if (t < 16) {
            float s = 0.f;
            #pragma unroll
            for (int gg = 0; gg < 16; ++gg) s += sm.red[bsel][gg][t];
            s *= Zinv;
            float sq = s * s;
            #pragma unroll
            for (int off = 8; off; off >>= 1)
                sq += __shfl_xor_sync(0x0000FFFFu, sq, off);
            float v = s * sqrtf(sq) / (1.0f + sq);
            sm.vv[bsel][t] = v;
            if (it == 2)                 // final iteration: emit output
                out[(c * kB + b) * kCo + t] = v;
        }
        __syncthreads();

        if (it == 1) {
            // agreement: lg[n] += dot(u[n,:], v)
            for (int n = t; n < kN; n += 256) {
                float d = 0.f;
                #pragma unroll
                for (int cc = 0; cc < kCo; ++cc)
                    d += U[n * kUP + cc] * sm.vv[bsel][cc];
                LG[n] += d;
            }
            __syncthreads();
        }
    }
}

extern "C" void kernel_launch(void* const* d_in, const int* in_sizes, int n_in,
                              void* d_out, int out_size)
{
    const float* x = (const float*)d_in[0];
    const float* W = (const float*)d_in[1];
    float* out = (float*)d_out;

    cudaFuncSetAttribute(caps_routing_kernel,
                         cudaFuncAttributeMaxDynamicSharedMemorySize,
                         (int)sizeof(Smem));
    dim3 grid(kB / kBT, kC);
    caps_routing_kernel<<<grid, kThreads, sizeof(Smem)>>>(x, W, out);
}

// round 3
// speedup vs baseline: 1.4014x; 1.4014x over previous
#include <cuda_runtime.h>

// CapsNet dynamic routing, fully fused, register-resident routing state.
// x:  [B=256, N=1152, Ci=8]  fp32
// W:  [C=10, N=1152, Ci=8, Co=16] fp32
// out:[C, B, Co] fp32
//
// Block = (c, pair of b). Phase 1 computes priors u with coalesced W loads and
// writes them ONCE to SMEM (co-major, padded stride -> conflict-free). Phase 2
// pulls each thread's 4 rows x 16 co into registers; all 3 routing iterations
// run on registers + butterfly multi-value shfl reductions + tiny SMEM scratch.
// Routing for b0/b1 is decoupled with named barriers (288 threads = 9 warps each).

static constexpr int kB  = 256;
static constexpr int kN  = 1152;
static constexpr int kCi = 8;
static constexpr int kC  = 10;
static constexpr int kCo = 16;
static constexpr int kBT = 2;          // batches per block
static constexpr int kThreads = 576;   // 18 warps
static constexpr int kTPB = 288;       // routing threads per b (9 warps)
static constexpr int kRows = 4;        // rows per routing thread (1152/288)
static constexpr int kS   = 1154;      // u_t co-plane stride (== 2 mod 8 -> conflict-free)

struct Smem {
    float ut[kBT * kCo * kS];   // u transposed: ut[(b*16+co)*kS + n]
    float red[kBT][9][kCo];     // per-warp s partials
    float msc[kBT][9];          // per-warp max scratch
    float zsc[kBT][9];          // per-warp Z scratch
    float vv[kBT][kCo];         // squashed v
};

__device__ __forceinline__ void barb(int b) {
    // named barrier per-b: id 1 or 2, 288 threads (9 aligned warps)
    asm volatile("bar.sync %0, %1;" :: "r"(b + 1), "r"(kTPB) : "memory");
}

// Butterfly reduction of 16 values across a warp: 15+1 shfls.
// On exit, a[0] of lane l holds the warp total for co = bitrev4(l & 15).
__device__ __forceinline__ float warp_reduce16(float a[kCo], int lane) {
    #pragma unroll
    for (int b = 0; b < 4; ++b) {
        const int off = 1 << b;
        const bool hi = (lane >> b) & 1;
        const int h = 16 >> (b + 1);         // 8,4,2,1
        #pragma unroll
        for (int i = 0; i < h; ++i) {
            float send = hi ? a[i] : a[i + h];
            float recv = __shfl_xor_sync(0xFFFFFFFFu, send, off);
            a[i] = (hi ? a[i + h] : a[i]) + recv;
        }
    }
    return a[0] + __shfl_xor_sync(0xFFFFFFFFu, a[0], 16);
}

__device__ __forceinline__ int bitrev4(int l) {
    return ((l & 1) << 3) | ((l & 2) << 1) | ((l & 4) >> 1) | ((l & 8) >> 3);
}

__global__ __launch_bounds__(kThreads, 1)
void caps_routing_kernel(const float* __restrict__ x,
                         const float* __restrict__ W,
                         float* __restrict__ out)
{
    extern __shared__ unsigned char smem_u8[];
    Smem& sm = *reinterpret_cast<Smem*>(smem_u8);

    const int tid = threadIdx.x;
    const int c  = blockIdx.y;
    const int b0 = blockIdx.x * kBT;

    // ---------------- Phase 1: priors -------------------------------------
    // thread -> (co4 = tid&3 covering 4 Co via float4, nloc = tid>>2), 8 passes of 144 n.
    {
        const int co4  = tid & 3;
        const int nloc = tid >> 2;                   // 0..143
        const float4* __restrict__ W4 = reinterpret_cast<const float4*>(W);
        const float4* __restrict__ X4 = reinterpret_cast<const float4*>(x);

        #pragma unroll 1
        for (int pass = 0; pass < kN / 144; ++pass) {
            const int n = pass * 144 + nloc;

            float4 xa0 = X4[(b0 * kN + n) * 2 + 0];
            float4 xb0 = X4[(b0 * kN + n) * 2 + 1];
            float4 xa1 = X4[((b0 + 1) * kN + n) * 2 + 0];
            float4 xb1 = X4[((b0 + 1) * kN + n) * 2 + 1];
            float x0v[8] = {xa0.x, xa0.y, xa0.z, xa0.w, xb0.x, xb0.y, xb0.z, xb0.w};
            float x1v[8] = {xa1.x, xa1.y, xa1.z, xa1.w, xb1.x, xb1.y, xb1.z, xb1.w};

            float4 a0 = make_float4(0.f, 0.f, 0.f, 0.f);
            float4 a1 = make_float4(0.f, 0.f, 0.f, 0.f);
            const int wbase = ((c * kN + n) * kCi) * 4 + co4;
            #pragma unroll
            for (int i = 0; i < kCi; ++i) {
                float4 w = W4[wbase + i * 4];
                a0.x += x0v[i] * w.x; a0.y += x0v[i] * w.y;
                a0.z += x0v[i] * w.z; a0.w += x0v[i] * w.w;
                a1.x += x1v[i] * w.x; a1.y += x1v[i] * w.y;
                a1.z += x1v[i] * w.z; a1.w += x1v[i] * w.w;
            }
            // transposed store: ut[(b*16 + co)*kS + n], co = 4*co4 + k
            const int cb = 4 * co4;
            float av0[4] = {a0.x, a0.y, a0.z, a0.w};
            float av1[4] = {a1.x, a1.y, a1.z, a1.w};
            #pragma unroll
            for (int k = 0; k < 4; ++k) {
                sm.ut[(0 * kCo + cb + k) * kS + n] = av0[k];
                sm.ut[(1 * kCo + cb + k) * kS + n] = av1[k];
            }
        }
    }
    __syncthreads();

    // ---------------- Phase 2: routing ------------------------------------
    const int bsel = (tid >= kTPB) ? 1 : 0;
    const int t    = tid - bsel * kTPB;       // 0..287
    const int lane = t & 31;
    const int wrp  = t >> 5;                  // 0..8
    const int bg   = b0 + bsel;
    const int corev = bitrev4(lane & 15);     // co this lane owns after reduce16

    const float* __restrict__ UTB = &sm.ut[bsel * kCo * kS];

    // pull this thread's 4 rows into registers
    float u[kRows][kCo];
    #pragma unroll
    for (int k = 0; k < kRows; ++k) {
        const int n = t + k * kTPB;
        #pragma unroll
        for (int co = 0; co < kCo; ++co)
            u[k][co] = UTB[co * kS + n];
    }

    float lg[kRows];

    // ---- iteration 0: uniform probs ----
    {
        float r[kCo];
        #pragma unroll
        for (int co = 0; co < kCo; ++co)
            r[co] = u[0][co] + u[1][co] + u[2][co] + u[3][co];
        float tot = warp_reduce16(r, lane);
        if (lane < 16) sm.red[bsel][wrp][corev] = tot;
        barb(bsel);

        if (t < kCo) {
            float s = 0.f;
            #pragma unroll
            for (int w = 0; w < 9; ++w) s += sm.red[bsel][w][t];
            s *= (1.0f / kN);
            float sq = s * s;
            #pragma unroll
            for (int off = 8; off; off >>= 1)
                sq += __shfl_xor_sync(0x0000FFFFu, sq, off);
            sm.vv[bsel][t] = s * sqrtf(sq) / (1.0f + sq);
        }
        barb(bsel);

        float v[kCo];
        #pragma unroll
        for (int co = 0; co < kCo; ++co) v[co] = sm.vv[bsel][co];
        #pragma unroll
        for (int k = 0; k < kRows; ++k) {
            float d = 0.f;
            #pragma unroll
            for (int co = 0; co < kCo; ++co) d += u[k][co] * v[co];
            lg[k] = d;
        }
    }

    // ---- iterations 1, 2 ----
    #pragma unroll 1
    for (int it = 1; it < 3; ++it) {
        // half-block max of logits
        float m = fmaxf(fmaxf(lg[0], lg[1]), fmaxf(lg[2], lg[3]));
        #pragma unroll
        for (int off = 16; off; off >>= 1)
            m = fmaxf(m, __shfl_xor_sync(0xFFFFFFFFu, m, off));
        if (lane == 0) sm.msc[bsel][wrp] = m;
        barb(bsel);
        float mm = sm.msc[bsel][0];
        #pragma unroll
        for (int w = 1; w < 9; ++w) mm = fmaxf(mm, sm.msc[bsel][w]);

        // e = exp(lg - mm); partial Z and partial s
        float e[kRows];
        float zp = 0.f;
        #pragma unroll
        for (int k = 0; k < kRows; ++k) {
            e[k] = __expf(lg[k] - mm);
            zp += e[k];
        }
        #pragma unroll
        for (int off = 16; off; off >>= 1)
            zp += __shfl_xor_sync(0xFFFFFFFFu, zp, off);

        float r[kCo];
        #pragma unroll
        for (int co = 0; co < kCo; ++co)
            r[co] = e[0] * u[0][co] + e[1] * u[1][co]
                  + e[2] * u[2][co] + e[3] * u[3][co];
        float tot = warp_reduce16(r, lane);
        if (lane == 0) sm.zsc[bsel][wrp] = zp;
        if (lane < 16) sm.red[bsel][wrp][corev] = tot;
        barb(bsel);

        if (t < kCo) {
            float Z = 0.f, s = 0.f;
            #pragma unroll
            for (int w = 0; w < 9; ++w) { Z += sm.zsc[bsel][w]; s += sm.red[bsel][w][t]; }
            s /= Z;
            float sq = s * s;
            #pragma unroll
            for (int off = 8; off; off >>= 1)
                sq += __shfl_xor_sync(0x0000FFFFu, sq, off);
            float v = s * sqrtf(sq) / (1.0f + sq);
            sm.vv[bsel][t] = v;
            if (it == 2)
                out[(c * kB + bg) * kCo + t] = v;
        }
        barb(bsel);

        if (it == 1) {
            float v[kCo];
            #pragma unroll
            for (int co = 0; co < kCo; ++co) v[co] = sm.vv[bsel][co];
            #pragma unroll
            for (int k = 0; k < kRows; ++k) {
                float d = 0.f;
                #pragma unroll
                for (int co = 0; co < kCo; ++co) d += u[k][co] * v[co];
                lg[k] += d;
            }
        }
    }
}

extern "C" void kernel_launch(void* const* d_in, const int* in_sizes, int n_in,
                              void* d_out, int out_size)
{
    const float* x = (const float*)d_in[0];
    const float* W = (const float*)d_in[1];
    float* out = (float*)d_out;

    cudaFuncSetAttribute(caps_routing_kernel,
                         cudaFuncAttributeMaxDynamicSharedMemorySize,
                         (int)sizeof(Smem));
    dim3 grid(kB / kBT, kC);
    caps_routing_kernel<<<grid, kThreads, sizeof(Smem)>>>(x, W, out);
}

// round 4
// speedup vs baseline: 1.9154x; 1.3667x over previous
#include <cuda_runtime.h>
#include <cuda_fp16.h>

// CapsNet dynamic routing, fully fused.
// x:  [B=256, N=1152, Ci=8]  fp32
// W:  [C=10, N=1152, Ci=8, Co=16] fp32
// out:[C, B, Co] fp32
//
// Kernel 1 (prep): W -> fp16, transposed to lane-major layout so phase-1 W
// loads are fully-coalesced 512B warp transactions (128B/wavefront):
//   Wt[(((c*36+g32)*8+i)*2+h)*32 + nl][8 halfs],  n = g32*32+nl, co = 8h+j
// Kernel 2: per (c, b-pair) block computes priors u into SMEM (fp32, n-major,
// stride 20 floats: 16B-aligned + conflict-free for STS.128/LDS.128), then
// runs 3 routing iterations register-resident (butterfly shfl reductions,
// named barriers decouple the two b's).

static constexpr int kB  = 256;
static constexpr int kN  = 1152;
static constexpr int kCi = 8;
static constexpr int kC  = 10;
static constexpr int kCo = 16;
static constexpr int kBT = 2;          // batches per block
static constexpr int kThreads = 576;   // 18 warps
static constexpr int kTPB = 288;       // routing threads per b (9 warps)
static constexpr int kRows = 4;        // rows per routing thread (1152/288)
static constexpr int kS   = 20;        // u row stride (floats): 80B, aligned + conflict-free

static constexpr int kWTotal = kC * kN * kCi * kCo;   // 1,474,560 halfs

__device__ __half g_Wt[kWTotal];

struct Smem {
    float ut[kBT][kN][kS];      // priors, n-major padded rows (184,320 B)
    float red[kBT][9][kCo];     // per-warp s partials
    float msc[kBT][9];          // per-warp max scratch
    float zsc[kBT][9];          // per-warp Z scratch
    float vv[kBT][kCo];         // squashed v
};

// ---------------- prep: transpose + fp16 convert ---------------------------
__global__ void transpose_W_kernel(const float* __restrict__ W) {
    int o2 = blockIdx.x * blockDim.x + threadIdx.x;   // half2 index
    if (o2 >= kWTotal / 2) return;
    int o = o2 * 2;
    int j   = o & 7;            // co8 (even; pair j, j+1)
    int nl  = (o >> 3) & 31;
    int h   = (o >> 8) & 1;
    int i   = (o >> 9) & 7;
    int g32 = (o >> 12) % 36;
    int c   = o / (36 * 4096);
    int n   = g32 * 32 + nl;
    const float* src = W + (((size_t)(c * kN + n) * kCi + i) * kCo) + h * 8 + j;
    __half2 v = __floats2half2_rn(src[0], src[1]);
    *reinterpret_cast<__half2*>(g_Wt + o) = v;
}

// ---------------- helpers ---------------------------------------------------
__device__ __forceinline__ void barb(int b) {
    asm volatile("bar.sync %0, %1;" :: "r"(b + 1), "r"(kTPB) : "memory");
}

// Butterfly reduction of 16 values across a warp.
// On exit, return of lane l holds the warp total for co = bitrev4(l & 15).
__device__ __forceinline__ float warp_reduce16(float a[kCo], int lane) {
    #pragma unroll
    for (int b = 0; b < 4; ++b) {
        const int off = 1 << b;
        const bool hi = (lane >> b) & 1;
        const int hh = 16 >> (b + 1);        // 8,4,2,1
        #pragma unroll
        for (int i = 0; i < hh; ++i) {
            float send = hi ? a[i] : a[i + hh];
            float recv = __shfl_xor_sync(0xFFFFFFFFu, send, off);
            a[i] = (hi ? a[i + hh] : a[i]) + recv;
        }
    }
    return a[0] + __shfl_xor_sync(0xFFFFFFFFu, a[0], 16);
}

__device__ __forceinline__ int bitrev4(int l) {
    return ((l & 1) << 3) | ((l & 2) << 1) | ((l & 4) >> 1) | ((l & 8) >> 3);
}

// ---------------- main ------------------------------------------------------
__global__ __launch_bounds__(kThreads, 1)
void caps_routing_kernel(const float* __restrict__ x,
                         float* __restrict__ out)
{
    extern __shared__ unsigned char smem_u8[];
    Smem& sm = *reinterpret_cast<Smem*>(smem_u8);

    const int tid = threadIdx.x;
    const int c  = blockIdx.y;
    const int b0 = blockIdx.x * kBT;

    // ---------------- Phase 1: priors -------------------------------------
    // warp w: h = w&1 (co-oct), covers 32 consecutive n per pass.
    {
        const int lane = tid & 31;
        const int wrp  = tid >> 5;
        const int h    = wrp & 1;                        // co oct: co = 8h + j
        const int nloc = (wrp >> 1) * 32 + lane;         // 0..287
        const float4* __restrict__ X4 = reinterpret_cast<const float4*>(x);
        const uint4*  __restrict__ Wt4 = reinterpret_cast<const uint4*>(g_Wt);

        #pragma unroll 1
        for (int pass = 0; pass < kN / 288; ++pass) {
            const int n   = pass * 288 + nloc;
            const int g32 = n >> 5;
            const int nl  = n & 31;

            float4 xa0 = X4[(b0 * kN + n) * 2 + 0];
            float4 xb0 = X4[(b0 * kN + n) * 2 + 1];
            float4 xa1 = X4[((b0 + 1) * kN + n) * 2 + 0];
            float4 xb1 = X4[((b0 + 1) * kN + n) * 2 + 1];
            float x0v[8] = {xa0.x, xa0.y, xa0.z, xa0.w, xb0.x, xb0.y, xb0.z, xb0.w};
            float x1v[8] = {xa1.x, xa1.y, xa1.z, xa1.w, xb1.x, xb1.y, xb1.z, xb1.w};

            float a0[8] = {0,0,0,0,0,0,0,0};
            float a1[8] = {0,0,0,0,0,0,0,0};
            // uint4 chunk index: (((c*36+g32)*8+i)*2+h)*32 + nl  -> i stride 64
            size_t base = ((size_t)((c * 36 + g32) * 16 + h)) * 32 + nl;
            #pragma unroll
            for (int i = 0; i < kCi; ++i) {
                uint4 w = Wt4[base + (size_t)i * 64];
                const __half2* hp = reinterpret_cast<const __half2*>(&w);
                const float xi0 = x0v[i], xi1 = x1v[i];
                #pragma unroll
                for (int q = 0; q < 4; ++q) {
                    float2 f = __half22float2(hp[q]);
                    a0[2*q]   += xi0 * f.x;  a0[2*q+1] += xi0 * f.y;
                    a1[2*q]   += xi1 * f.x;  a1[2*q+1] += xi1 * f.y;
                }
            }
            float4* p0 = reinterpret_cast<float4*>(&sm.ut[0][n][8 * h]);
            float4* p1 = reinterpret_cast<float4*>(&sm.ut[1][n][8 * h]);
            p0[0] = make_float4(a0[0], a0[1], a0[2], a0[3]);
            p0[1] = make_float4(a0[4], a0[5], a0[6], a0[7]);
            p1[0] = make_float4(a1[0], a1[1], a1[2], a1[3]);
            p1[1] = make_float4(a1[4], a1[5], a1[6], a1[7]);
        }
    }
    __syncthreads();

    // ---------------- Phase 2: routing ------------------------------------
    const int bsel = (tid >= kTPB) ? 1 : 0;
    const int t    = tid - bsel * kTPB;       // 0..287
    const int lane = t & 31;
    const int wrp  = t >> 5;                  // 0..8
    const int bg   = b0 + bsel;
    const int corev = bitrev4(lane & 15);

    const float* __restrict__ UTB = &sm.ut[bsel][0][0];

    // pull this thread's 4 rows into registers (4x LDS.128 per row)
    float u[kRows][kCo];
    #pragma unroll
    for (int k = 0; k < kRows; ++k) {
        const int n = t + k * kTPB;
        const float4* r = reinterpret_cast<const float4*>(&UTB[n * kS]);
        #pragma unroll
        for (int q = 0; q < 4; ++q) {
            float4 v = r[q];
            u[k][4*q+0] = v.x; u[k][4*q+1] = v.y;
            u[k][4*q+2] = v.z; u[k][4*q+3] = v.w;
        }
    }

    float lg[kRows];

    // ---- iteration 0: uniform probs ----
    {
        float r[kCo];
        #pragma unroll
        for (int co = 0; co < kCo; ++co)
            r[co] = u[0][co] + u[1][co] + u[2][co] + u[3][co];
        float tot = warp_reduce16(r, lane);
        if (lane < 16) sm.red[bsel][wrp][corev] = tot;
        barb(bsel);

        if (t < kCo) {
            float s = 0.f;
            #pragma unroll
            for (int w = 0; w < 9; ++w) s += sm.red[bsel][w][t];
            s *= (1.0f / kN);
            float sq = s * s;
            #pragma unroll
            for (int off = 8; off; off >>= 1)
                sq += __shfl_xor_sync(0x0000FFFFu, sq, off);
            sm.vv[bsel][t] = s * sqrtf(sq) / (1.0f + sq);
        }
        barb(bsel);

        float v[kCo];
        #pragma unroll
        for (int co = 0; co < kCo; ++co) v[co] = sm.vv[bsel][co];
        #pragma unroll
        for (int k = 0; k < kRows; ++k) {
            float d = 0.f;
            #pragma unroll
            for (int co = 0; co < kCo; ++co) d += u[k][co] * v[co];
            lg[k] = d;
        }
    }

    // ---- iterations 1, 2 ----
    #pragma unroll 1
    for (int it = 1; it < 3; ++it) {
        float m = fmaxf(fmaxf(lg[0], lg[1]), fmaxf(lg[2], lg[3]));
        #pragma unroll
        for (int off = 16; off; off >>= 1)
            m = fmaxf(m, __shfl_xor_sync(0xFFFFFFFFu, m, off));
        if (lane == 0) sm.msc[bsel][wrp] = m;
        barb(bsel);
        float mm = sm.msc[bsel][0];
        #pragma unroll
        for (int w = 1; w < 9; ++w) mm = fmaxf(mm, sm.msc[bsel][w]);

        float e[kRows];
        float zp = 0.f;
        #pragma unroll
        for (int k = 0; k < kRows; ++k) {
            e[k] = __expf(lg[k] - mm);
            zp += e[k];
        }
        #pragma unroll
        for (int off = 16; off; off >>= 1)
            zp += __shfl_xor_sync(0xFFFFFFFFu, zp, off);

        float r[kCo];
        #pragma unroll
        for (int co = 0; co < kCo; ++co)
            r[co] = e[0] * u[0][co] + e[1] * u[1][co]
                  + e[2] * u[2][co] + e[3] * u[3][co];
        float tot = warp_reduce16(r, lane);
        if (lane == 0) sm.zsc[bsel][wrp] = zp;
        if (lane < 16) sm.red[bsel][wrp][corev] = tot;
        barb(bsel);

        if (t < kCo) {
            float Z = 0.f, s = 0.f;
            #pragma unroll
            for (int w = 0; w < 9; ++w) { Z += sm.zsc[bsel][w]; s += sm.red[bsel][w][t]; }
            s /= Z;
            float sq = s * s;
            #pragma unroll
            for (int off = 8; off; off >>= 1)
                sq += __shfl_xor_sync(0x0000FFFFu, sq, off);
            float v = s * sqrtf(sq) / (1.0f + sq);
            sm.vv[bsel][t] = v;
            if (it == 2)
                out[(c * kB + bg) * kCo + t] = v;
        }
        barb(bsel);

        if (it == 1) {
            float v[kCo];
            #pragma unroll
            for (int co = 0; co < kCo; ++co) v[co] = sm.vv[bsel][co];
            #pragma unroll
            for (int k = 0; k < kRows; ++k) {
                float d = 0.f;
                #pragma unroll
                for (int co = 0; co < kCo; ++co) d += u[k][co] * v[co];
                lg[k] += d;
            }
        }
    }
}

extern "C" void kernel_launch(void* const* d_in, const int* in_sizes, int n_in,
                              void* d_out, int out_size)
{
    const float* x = (const float*)d_in[0];
    const float* W = (const float*)d_in[1];
    float* out = (float*)d_out;

    // prep: fp16 transposed W (deterministic, idempotent, graph-capturable)
    const int prep_threads = 256;
    const int prep_blocks = (kWTotal / 2 + prep_threads - 1) / prep_threads;
    transpose_W_kernel<<<prep_blocks, prep_threads>>>(W);

    cudaFuncSetAttribute(caps_routing_kernel,
                         cudaFuncAttributeMaxDynamicSharedMemorySize,
                         (int)sizeof(Smem));
    dim3 grid(kB / kBT, kC);
    caps_routing_kernel<<<grid, kThreads, sizeof(Smem)>>>(x, out);
}